// round 1
// baseline (speedup 1.0000x reference)
#include <cuda_runtime.h>
#include <cuda_bf16.h>
#include <math.h>

#define T_   2048
#define DM_  4096
#define H_   16
#define HD_  256
#define RD_  64
#define DFF_ 16384
#define EPS_ 1e-5f

// ---------------- scratch (allocation-free: __device__ globals) ----------------
__device__ float g_ln   [(long)T_ * DM_];        // 32 MB
__device__ float g_qkv  [(long)T_ * 3 * DM_];    // 96 MB
__device__ float g_scores[(long)H_ * T_ * T_];   // 256 MB
__device__ float g_ctx  [(long)T_ * DM_];        // 32 MB
__device__ float g_attn [(long)T_ * DM_];        // 32 MB
__device__ float g_mlph [(long)T_ * DFF_];       // 128 MB

// ---------------- LayerNorm ----------------
__global__ void ln_kernel(const float* __restrict__ x,
                          const float* __restrict__ g,
                          const float* __restrict__ b,
                          float* __restrict__ out)
{
    int row = blockIdx.x;
    const float* xr = x + (long)row * DM_;
    float* orow = out + (long)row * DM_;
    int tid = threadIdx.x;                 // 256 threads, 16 elems each

    float s = 0.f, s2 = 0.f;
    #pragma unroll 4
    for (int i = tid; i < DM_; i += 256) {
        float v = xr[i];
        s += v; s2 += v * v;
    }
    // warp reduce
    for (int o = 16; o > 0; o >>= 1) {
        s  += __shfl_xor_sync(0xffffffff, s,  o);
        s2 += __shfl_xor_sync(0xffffffff, s2, o);
    }
    __shared__ float ws[8], ws2[8];
    int wid = tid >> 5, lid = tid & 31;
    if (lid == 0) { ws[wid] = s; ws2[wid] = s2; }
    __syncthreads();
    if (wid == 0) {
        s  = (lid < 8) ? ws[lid]  : 0.f;
        s2 = (lid < 8) ? ws2[lid] : 0.f;
        for (int o = 4; o > 0; o >>= 1) {
            s  += __shfl_xor_sync(0xffffffff, s,  o);
            s2 += __shfl_xor_sync(0xffffffff, s2, o);
        }
        if (lid == 0) { ws[0] = s; ws2[0] = s2; }
    }
    __syncthreads();
    float mu  = ws[0]  * (1.0f / DM_);
    float var = ws2[0] * (1.0f / DM_) - mu * mu;
    float rs  = rsqrtf(var + EPS_);
    #pragma unroll 4
    for (int i = tid; i < DM_; i += 256) {
        orow[i] = (xr[i] - mu) * rs * g[i] + b[i];
    }
}

// ---------------- RoPE (GPT-J interleaved), in-place on qkv ----------------
__global__ void rope_kernel(float* __restrict__ qkv, const int* __restrict__ pos)
{
    int t    = blockIdx.y;
    int h    = blockIdx.x & (H_ - 1);
    int isK  = blockIdx.x >> 4;            // 0 = q, 1 = k
    int lane = threadIdx.x;                // 0..31 (RD/2 pairs)

    float* p = qkv + (long)t * (3 * DM_) + (long)isK * DM_ + (long)h * HD_;
    float freq = powf(10000.0f, -(float)lane / 32.0f);
    float ang  = (float)pos[t] * freq;
    float sn, cs;
    sincosf(ang, &sn, &cs);
    float x1 = p[2 * lane], x2 = p[2 * lane + 1];
    p[2 * lane]     = x1 * cs - x2 * sn;
    p[2 * lane + 1] = x2 * cs + x1 * sn;
}

// ---------------- row softmax (in place) ----------------
__global__ void softmax_kernel(float* __restrict__ scores)
{
    long row = blockIdx.x;                 // H*T rows of length T
    float* p = scores + row * T_;
    int tid = threadIdx.x;                 // 256

    float mx = -3.4e38f;
    for (int i = tid; i < T_; i += 256) mx = fmaxf(mx, p[i]);
    for (int o = 16; o > 0; o >>= 1) mx = fmaxf(mx, __shfl_xor_sync(0xffffffff, mx, o));
    __shared__ float sm[8];
    int wid = tid >> 5, lid = tid & 31;
    if (lid == 0) sm[wid] = mx;
    __syncthreads();
    if (tid < 8) {
        mx = sm[tid];
        for (int o = 4; o > 0; o >>= 1) mx = fmaxf(mx, __shfl_xor_sync(0xff, mx, o));
        if (tid == 0) sm[0] = mx;
    }
    __syncthreads();
    mx = sm[0];

    float sum = 0.f;
    for (int i = tid; i < T_; i += 256) {
        float e = __expf(p[i] - mx);
        p[i] = e;
        sum += e;
    }
    for (int o = 16; o > 0; o >>= 1) sum += __shfl_xor_sync(0xffffffff, sum, o);
    __shared__ float ss[8];
    if (lid == 0) ss[wid] = sum;
    __syncthreads();
    if (tid < 8) {
        sum = ss[tid];
        for (int o = 4; o > 0; o >>= 1) sum += __shfl_xor_sync(0xff, sum, o);
        if (tid == 0) ss[0] = sum;
    }
    __syncthreads();
    float inv = 1.0f / ss[0];
    for (int i = tid; i < T_; i += 256) p[i] *= inv;
}

// ---------------- generic strided SGEMM with fused epilogues ----------------
// C[m,n] (+z*hsC) = sum_k A[m*rsA + k + z*hsA] * B[k*rsB + n*csB + z*hsB]
// mode 0: plain        mode 1: v*scale, causal mask (n>m -> -big)
// mode 2: gelu(v+bias) mode 3: v + bias[n] + add1[m,n] + add2[m,n]
#define BM 128
#define BN 128
#define BK 8
#define TM 8
#define TN 8

__global__ __launch_bounds__(256, 2)
void sgemm_kernel(const float* __restrict__ A, long rsA, long hsA,
                  const float* __restrict__ B, long rsB, long csB, long hsB,
                  float* __restrict__ C, long ldc, long hsC,
                  int M, int N, int K,
                  int mode, float scale,
                  const float* __restrict__ bias,
                  const float* __restrict__ add1,
                  const float* __restrict__ add2)
{
    __shared__ float As[BK][BM];
    __shared__ float Bs[BK][BN];

    A += (long)blockIdx.z * hsA;
    B += (long)blockIdx.z * hsB;
    C += (long)blockIdx.z * hsC;

    const int tid  = threadIdx.x;
    const int m0   = blockIdx.y * BM;
    const int n0   = blockIdx.x * BN;
    const int trow = tid >> 4;             // 0..15
    const int tcol = tid & 15;             // 0..15

    float acc[TM][TN];
    #pragma unroll
    for (int i = 0; i < TM; i++)
        #pragma unroll
        for (int j = 0; j < TN; j++) acc[i][j] = 0.f;

    const int aRow  = tid >> 1;            // 0..127
    const int aCol4 = (tid & 1) * 4;       // 0 or 4
    const int bRow  = tid >> 5;            // 0..7
    const int bCol4 = (tid & 31) * 4;      // 0..124

    for (int k0 = 0; k0 < K; k0 += BK) {
        #pragma unroll
        for (int j = 0; j < 4; j++)
            As[aCol4 + j][aRow] = A[(long)(m0 + aRow) * rsA + (k0 + aCol4 + j)];
        #pragma unroll
        for (int j = 0; j < 4; j++)
            Bs[bRow][bCol4 + j] = B[(long)(k0 + bRow) * rsB + (long)(n0 + bCol4 + j) * csB];
        __syncthreads();

        #pragma unroll
        for (int kk = 0; kk < BK; kk++) {
            float4 a0 = *reinterpret_cast<const float4*>(&As[kk][trow * TM]);
            float4 a1 = *reinterpret_cast<const float4*>(&As[kk][trow * TM + 4]);
            float4 b0 = *reinterpret_cast<const float4*>(&Bs[kk][tcol * TN]);
            float4 b1 = *reinterpret_cast<const float4*>(&Bs[kk][tcol * TN + 4]);
            float ra[TM] = {a0.x, a0.y, a0.z, a0.w, a1.x, a1.y, a1.z, a1.w};
            float rb[TN] = {b0.x, b0.y, b0.z, b0.w, b1.x, b1.y, b1.z, b1.w};
            #pragma unroll
            for (int i = 0; i < TM; i++)
                #pragma unroll
                for (int j = 0; j < TN; j++)
                    acc[i][j] = fmaf(ra[i], rb[j], acc[i][j]);
        }
        __syncthreads();
    }

    #pragma unroll
    for (int i = 0; i < TM; i++) {
        int m = m0 + trow * TM + i;
        #pragma unroll
        for (int j = 0; j < TN; j++) {
            int n = n0 + tcol * TN + j;
            float v = acc[i][j];
            if (mode == 1) {
                v = (n <= m) ? v * scale : -3.0e38f;
            } else if (mode == 2) {
                v += bias[n];
                float x3 = v * v * v;
                v = 0.5f * v * (1.0f + tanhf(0.7978845608028654f * (v + 0.044715f * x3)));
            } else if (mode == 3) {
                v += bias[n] + add1[(long)m * ldc + n] + add2[(long)m * ldc + n];
            }
            C[(long)m * ldc + n] = v;
        }
    }
}

// ---------------- launch ----------------
extern "C" void kernel_launch(void* const* d_in, const int* in_sizes, int n_in,
                              void* d_out, int out_size)
{
    const int*   positions = (const int*)  d_in[0];
    const float* hidden    = (const float*)d_in[1];
    const float* ln_g      = (const float*)d_in[2];
    const float* ln_b      = (const float*)d_in[3];
    const float* w_qkv     = (const float*)d_in[4];
    const float* w_out     = (const float*)d_in[5];
    const float* w_fc_in   = (const float*)d_in[6];
    const float* b_fc_in   = (const float*)d_in[7];
    const float* w_fc_out  = (const float*)d_in[8];
    const float* b_fc_out  = (const float*)d_in[9];
    float* out = (float*)d_out;

    float *ln, *qkv, *scores, *ctx, *attn, *mlph;
    cudaGetSymbolAddress((void**)&ln,     g_ln);
    cudaGetSymbolAddress((void**)&qkv,    g_qkv);
    cudaGetSymbolAddress((void**)&scores, g_scores);
    cudaGetSymbolAddress((void**)&ctx,    g_ctx);
    cudaGetSymbolAddress((void**)&attn,   g_attn);
    cudaGetSymbolAddress((void**)&mlph,   g_mlph);

    // 1. LayerNorm
    ln_kernel<<<T_, 256>>>(hidden, ln_g, ln_b, ln);

    // 2. QKV GEMM: ln(2048x4096) @ w_qkv(4096x12288) -> qkv
    sgemm_kernel<<<dim3(3 * DM_ / BN, T_ / BM, 1), 256>>>(
        ln, DM_, 0, w_qkv, 3 * DM_, 1, 0, qkv, 3 * DM_, 0,
        T_, 3 * DM_, DM_, 0, 0.f, nullptr, nullptr, nullptr);

    // 3. RoPE in-place on q and k
    rope_kernel<<<dim3(2 * H_, T_), 32>>>(qkv, positions);

    // 4. scores[h] = q[h](2048x256) @ k[h]^T(256x2048), scaled + causal mask
    sgemm_kernel<<<dim3(T_ / BN, T_ / BM, H_), 256>>>(
        qkv, 3 * DM_, HD_,                       // A: q, head stride 256 cols
        qkv + DM_, 1, 3 * DM_, HD_,              // B: k^T (rsB=1 over d, csB=12288 over k)
        scores, T_, (long)T_ * T_,
        T_, T_, HD_, 1, 0.0625f, nullptr, nullptr, nullptr);

    // 5. softmax rows
    softmax_kernel<<<H_ * T_, 256>>>(scores);

    // 6. ctx[h] = probs[h](2048x2048) @ v[h](2048x256)
    sgemm_kernel<<<dim3(HD_ / BN, T_ / BM, H_), 256>>>(
        scores, T_, (long)T_ * T_,
        qkv + 2 * DM_, 3 * DM_, 1, HD_,
        ctx + 0, DM_, HD_,
        T_, HD_, T_, 0, 0.f, nullptr, nullptr, nullptr);

    // 7. attn_out = ctx @ w_out
    sgemm_kernel<<<dim3(DM_ / BN, T_ / BM, 1), 256>>>(
        ctx, DM_, 0, w_out, DM_, 1, 0, attn, DM_, 0,
        T_, DM_, DM_, 0, 0.f, nullptr, nullptr, nullptr);

    // 8. mlp hidden = gelu(ln @ w_fc_in + b_fc_in)
    sgemm_kernel<<<dim3(DFF_ / BN, T_ / BM, 1), 256>>>(
        ln, DM_, 0, w_fc_in, DFF_, 1, 0, mlph, DFF_, 0,
        T_, DFF_, DM_, 2, 0.f, b_fc_in, nullptr, nullptr);

    // 9. out = mlph @ w_fc_out + b_fc_out + attn_out + residual
    sgemm_kernel<<<dim3(DM_ / BN, T_ / BM, 1), 256>>>(
        mlph, DFF_, 0, w_fc_out, DM_, 1, 0, out, DM_, 0,
        T_, DM_, DFF_, 3, 0.f, b_fc_out, attn, hidden);
}

// round 4
// speedup vs baseline: 2.7194x; 2.7194x over previous
#include <cuda_runtime.h>
#include <cuda_bf16.h>
#include <math.h>
#include <stdint.h>

#define T_   2048
#define DM_  4096
#define H_   16
#define HD_  256
#define RD_  64
#define DFF_ 16384
#define EPS_ 1e-5f

// ==================== scratch (__device__ globals, no allocs) ====================
__device__ float g_qkv   [(long)T_ * 3 * DM_];
__device__ float g_scores[(long)H_ * T_ * T_];
__device__ float g_ctx   [(long)T_ * DM_];
__device__ float g_attn  [(long)T_ * DM_];
__device__ float g_kT    [(long)H_ * HD_ * T_];
// split activations (bf16 hi/lo)
__device__ __nv_bfloat16 g_ln_h  [(long)T_ * DM_];
__device__ __nv_bfloat16 g_ln_l  [(long)T_ * DM_];
__device__ __nv_bfloat16 g_ctx_h [(long)T_ * DM_];
__device__ __nv_bfloat16 g_ctx_l [(long)T_ * DM_];
__device__ __nv_bfloat16 g_mlph_h[(long)T_ * DFF_];
__device__ __nv_bfloat16 g_mlph_l[(long)T_ * DFF_];
// transposed + split weights: [N][K] bf16
__device__ __nv_bfloat16 g_wqkvT_h[(long)3 * DM_ * DM_];
__device__ __nv_bfloat16 g_wqkvT_l[(long)3 * DM_ * DM_];
__device__ __nv_bfloat16 g_woutT_h[(long)DM_ * DM_];
__device__ __nv_bfloat16 g_woutT_l[(long)DM_ * DM_];
__device__ __nv_bfloat16 g_wfiT_h [(long)DFF_ * DM_];
__device__ __nv_bfloat16 g_wfiT_l [(long)DFF_ * DM_];
__device__ __nv_bfloat16 g_wfoT_h [(long)DM_ * DFF_];
__device__ __nv_bfloat16 g_wfoT_l [(long)DM_ * DFF_];

// ==================== helpers ====================
__device__ __forceinline__ uint32_t smem_u32(const void* p) {
    uint32_t a;
    asm("{ .reg .u64 t; cvta.to.shared.u64 t, %1; cvt.u32.u64 %0, t; }" : "=r"(a) : "l"(p));
    return a;
}
#define CP_ASYNC16(dst, src) \
    asm volatile("cp.async.cg.shared.global [%0], [%1], 16;" :: "r"(dst), "l"(src) : "memory")
#define CP_COMMIT() asm volatile("cp.async.commit_group;" ::: "memory")
#define CP_WAIT1()  asm volatile("cp.async.wait_group 1;" ::: "memory")
#define LDMX4(r0, r1, r2, r3, addr) \
    asm volatile("ldmatrix.sync.aligned.m8n8.x4.shared.b16 {%0,%1,%2,%3}, [%4];" \
        : "=r"(r0), "=r"(r1), "=r"(r2), "=r"(r3) : "r"(addr))
#define MMA_BF16(c0, c1, c2, c3, a0, a1, a2, a3, b0, b1) \
    asm volatile("mma.sync.aligned.m16n8k16.row.col.f32.bf16.bf16.f32 " \
        "{%0,%1,%2,%3}, {%4,%5,%6,%7}, {%8,%9}, {%0,%1,%2,%3};" \
        : "+f"(c0), "+f"(c1), "+f"(c2), "+f"(c3) \
        : "r"(a0), "r"(a1), "r"(a2), "r"(a3), "r"(b0), "r"(b1))

__device__ __forceinline__ float gelu_f(float v) {
    return 0.5f * v * (1.0f + tanhf(0.7978845608028654f * (v + 0.044715f * v * v * v)));
}

// ==================== LayerNorm -> bf16 hi/lo split ====================
__global__ void ln_kernel(const float* __restrict__ x, const float* __restrict__ g,
                          const float* __restrict__ b,
                          __nv_bfloat16* __restrict__ oh, __nv_bfloat16* __restrict__ ol)
{
    int row = blockIdx.x;
    const float* xr = x + (long)row * DM_;
    int tid = threadIdx.x;
    float s = 0.f, s2 = 0.f;
    #pragma unroll 4
    for (int i = tid; i < DM_; i += 256) { float v = xr[i]; s += v; s2 += v * v; }
    for (int o = 16; o > 0; o >>= 1) {
        s  += __shfl_xor_sync(0xffffffff, s,  o);
        s2 += __shfl_xor_sync(0xffffffff, s2, o);
    }
    __shared__ float ws[8], ws2[8];
    int wid = tid >> 5, lid = tid & 31;
    if (lid == 0) { ws[wid] = s; ws2[wid] = s2; }
    __syncthreads();
    if (wid == 0) {
        s  = (lid < 8) ? ws[lid]  : 0.f;
        s2 = (lid < 8) ? ws2[lid] : 0.f;
        for (int o = 4; o > 0; o >>= 1) {
            s  += __shfl_xor_sync(0xffffffff, s,  o);
            s2 += __shfl_xor_sync(0xffffffff, s2, o);
        }
        if (lid == 0) { ws[0] = s; ws2[0] = s2; }
    }
    __syncthreads();
    float mu  = ws[0]  * (1.0f / DM_);
    float var = ws2[0] * (1.0f / DM_) - mu * mu;
    float rs  = rsqrtf(var + EPS_);
    #pragma unroll 4
    for (int i = tid; i < DM_; i += 256) {
        float y = (xr[i] - mu) * rs * g[i] + b[i];
        __nv_bfloat16 h = __float2bfloat16(y);
        oh[(long)row * DM_ + i] = h;
        ol[(long)row * DM_ + i] = __float2bfloat16(y - __bfloat162float(h));
    }
}

// ==================== elementwise fp32 -> bf16 hi/lo ====================
__global__ void split_kernel(const float* __restrict__ X,
                             __nv_bfloat16* __restrict__ Xh, __nv_bfloat16* __restrict__ Xl,
                             long n4)
{
    long i = ((long)blockIdx.x * 256 + threadIdx.x);
    if (i >= n4) return;
    float4 v = ((const float4*)X)[i];
    __nv_bfloat16 h0 = __float2bfloat16(v.x), h1 = __float2bfloat16(v.y),
                  h2 = __float2bfloat16(v.z), h3 = __float2bfloat16(v.w);
    uint2 ph, pl;
    ph.x = ((uint32_t)__bfloat16_as_ushort(h1) << 16) | __bfloat16_as_ushort(h0);
    ph.y = ((uint32_t)__bfloat16_as_ushort(h3) << 16) | __bfloat16_as_ushort(h2);
    __nv_bfloat16 l0 = __float2bfloat16(v.x - __bfloat162float(h0));
    __nv_bfloat16 l1 = __float2bfloat16(v.y - __bfloat162float(h1));
    __nv_bfloat16 l2 = __float2bfloat16(v.z - __bfloat162float(h2));
    __nv_bfloat16 l3 = __float2bfloat16(v.w - __bfloat162float(h3));
    pl.x = ((uint32_t)__bfloat16_as_ushort(l1) << 16) | __bfloat16_as_ushort(l0);
    pl.y = ((uint32_t)__bfloat16_as_ushort(l3) << 16) | __bfloat16_as_ushort(l2);
    ((uint2*)Xh)[i] = ph;
    ((uint2*)Xl)[i] = pl;
}

// ==================== weight transpose + bf16 split:  W[K,N] -> Th/Tl[N,K] ====================
__global__ void wconv_kernel(const float* __restrict__ W, int K, int N,
                             __nv_bfloat16* __restrict__ Th, __nv_bfloat16* __restrict__ Tl)
{
    __shared__ float tile[32][33];
    int n0 = blockIdx.x * 32, k0 = blockIdx.y * 32;
    int tx = threadIdx.x, ty = threadIdx.y;       // 32 x 8
    #pragma unroll
    for (int i = 0; i < 4; i++)
        tile[ty + 8 * i][tx] = W[(long)(k0 + ty + 8 * i) * N + n0 + tx];
    __syncthreads();
    #pragma unroll
    for (int i = 0; i < 4; i++) {
        float v = tile[tx][ty + 8 * i];
        __nv_bfloat16 h = __float2bfloat16(v);
        __nv_bfloat16 l = __float2bfloat16(v - __bfloat162float(h));
        long o = (long)(n0 + ty + 8 * i) * K + k0 + tx;
        Th[o] = h; Tl[o] = l;
    }
}

// ==================== k transpose per head ====================
__global__ void ktrans_kernel(const float* __restrict__ qkv, float* __restrict__ kT)
{
    __shared__ float tile[32][33];
    int h = blockIdx.z;
    int t0 = blockIdx.x * 32, d0 = blockIdx.y * 32;
    int tx = threadIdx.x, ty = threadIdx.y;
    #pragma unroll
    for (int i = 0; i < 4; i++)
        tile[ty + 8 * i][tx] = qkv[(long)(t0 + ty + 8 * i) * (3 * DM_) + DM_ + h * HD_ + d0 + tx];
    __syncthreads();
    #pragma unroll
    for (int i = 0; i < 4; i++)
        kT[(long)h * HD_ * T_ + (long)(d0 + ty + 8 * i) * T_ + t0 + tx] = tile[tx][ty + 8 * i];
}

// ==================== RoPE ====================
__global__ void rope_kernel(float* __restrict__ qkv, const int* __restrict__ pos)
{
    int t    = blockIdx.y;
    int h    = blockIdx.x & (H_ - 1);
    int isK  = blockIdx.x >> 4;
    int lane = threadIdx.x;
    float* p = qkv + (long)t * (3 * DM_) + (long)isK * DM_ + (long)h * HD_;
    float freq = powf(10000.0f, -(float)lane / 32.0f);
    float ang  = (float)pos[t] * freq;
    float sn, cs; sincosf(ang, &sn, &cs);
    float x1 = p[2 * lane], x2 = p[2 * lane + 1];
    p[2 * lane]     = x1 * cs - x2 * sn;
    p[2 * lane + 1] = x2 * cs + x1 * sn;
}

// ==================== softmax ====================
__global__ void softmax_kernel(float* __restrict__ scores)
{
    long row = blockIdx.x;
    float* p = scores + row * T_;
    int tid = threadIdx.x;
    float mx = -3.4e38f;
    for (int i = tid; i < T_; i += 256) mx = fmaxf(mx, p[i]);
    for (int o = 16; o > 0; o >>= 1) mx = fmaxf(mx, __shfl_xor_sync(0xffffffff, mx, o));
    __shared__ float sm[8];
    int wid = tid >> 5, lid = tid & 31;
    if (lid == 0) sm[wid] = mx;
    __syncthreads();
    if (tid < 8) {
        mx = sm[tid];
        for (int o = 4; o > 0; o >>= 1) mx = fmaxf(mx, __shfl_xor_sync(0xff, mx, o));
        if (tid == 0) sm[0] = mx;
    }
    __syncthreads();
    mx = sm[0];
    float sum = 0.f;
    for (int i = tid; i < T_; i += 256) { float e = __expf(p[i] - mx); p[i] = e; sum += e; }
    for (int o = 16; o > 0; o >>= 1) sum += __shfl_xor_sync(0xffffffff, sum, o);
    __shared__ float ss[8];
    if (lid == 0) ss[wid] = sum;
    __syncthreads();
    if (tid < 8) {
        sum = ss[tid];
        for (int o = 4; o > 0; o >>= 1) sum += __shfl_xor_sync(0xff, sum, o);
        if (tid == 0) ss[0] = sum;
    }
    __syncthreads();
    float inv = 1.0f / ss[0];
    for (int i = tid; i < T_; i += 256) p[i] *= inv;
}

// ==================== fp32 SGEMM (attention only) ====================
#define BM 128
#define BN 128
#define BK 8
#define TM 8
#define TN 8
__global__ __launch_bounds__(256, 2)
void sgemm_kernel(const float* __restrict__ A, long rsA, long hsA,
                  const float* __restrict__ B, long rsB, long csB, long hsB,
                  float* __restrict__ C, long ldc, long hsC,
                  int M, int N, int K, int mode, float scale)
{
    __shared__ float As[BK][BM];
    __shared__ float Bs[BK][BN];
    A += (long)blockIdx.z * hsA;
    B += (long)blockIdx.z * hsB;
    C += (long)blockIdx.z * hsC;
    const int tid = threadIdx.x;
    const int m0 = blockIdx.y * BM, n0 = blockIdx.x * BN;
    const int trow = tid >> 4, tcol = tid & 15;
    float acc[TM][TN];
    #pragma unroll
    for (int i = 0; i < TM; i++)
        #pragma unroll
        for (int j = 0; j < TN; j++) acc[i][j] = 0.f;
    const int aRow = tid >> 1, aCol4 = (tid & 1) * 4;
    const int bRow = tid >> 5, bCol4 = (tid & 31) * 4;
    for (int k0 = 0; k0 < K; k0 += BK) {
        #pragma unroll
        for (int j = 0; j < 4; j++)
            As[aCol4 + j][aRow] = A[(long)(m0 + aRow) * rsA + (k0 + aCol4 + j)];
        #pragma unroll
        for (int j = 0; j < 4; j++)
            Bs[bRow][bCol4 + j] = B[(long)(k0 + bRow) * rsB + (long)(n0 + bCol4 + j) * csB];
        __syncthreads();
        #pragma unroll
        for (int kk = 0; kk < BK; kk++) {
            float4 a0 = *reinterpret_cast<const float4*>(&As[kk][trow * TM]);
            float4 a1 = *reinterpret_cast<const float4*>(&As[kk][trow * TM + 4]);
            float4 b0 = *reinterpret_cast<const float4*>(&Bs[kk][tcol * TN]);
            float4 b1 = *reinterpret_cast<const float4*>(&Bs[kk][tcol * TN + 4]);
            float ra[TM] = {a0.x, a0.y, a0.z, a0.w, a1.x, a1.y, a1.z, a1.w};
            float rb[TN] = {b0.x, b0.y, b0.z, b0.w, b1.x, b1.y, b1.z, b1.w};
            #pragma unroll
            for (int i = 0; i < TM; i++)
                #pragma unroll
                for (int j = 0; j < TN; j++)
                    acc[i][j] = fmaf(ra[i], rb[j], acc[i][j]);
        }
        __syncthreads();
    }
    #pragma unroll
    for (int i = 0; i < TM; i++) {
        int m = m0 + trow * TM + i;
        #pragma unroll
        for (int j = 0; j < TN; j++) {
            int n = n0 + tcol * TN + j;
            float v = acc[i][j];
            if (mode == 1) v = (n <= m) ? v * scale : -3.0e38f;
            C[(long)m * ldc + n] = v;
        }
    }
}

// ==================== bf16-split mma.sync GEMM ====================
// C = (Ah+Al) @ (Bh+Bl)^T  with A[M][K] hi/lo bf16, B[N][K] hi/lo bf16, fp32 acc.
// 3 passes: Ah*Bh + Al*Bh + Ah*Bl.
// mode 0: fp32 C              mode 2: gelu(v + bias[n]) -> bf16 hi/lo (Ch, Cl)
// mode 3: v + bias[n] + add1[m,n] + add2[m,n] -> fp32 C
#define AST 40   // smem row stride in bf16 elems (80 bytes, conflict-free ldmatrix)
#define STAGE_B 40960
#define MAT_B   10240

__global__ __launch_bounds__(256, 2)
void gemm_mma(const __nv_bfloat16* __restrict__ Ah, const __nv_bfloat16* __restrict__ Al, long lda,
              const __nv_bfloat16* __restrict__ Bh, const __nv_bfloat16* __restrict__ Bl, long ldb,
              float* __restrict__ C, long ldc, int K, int mode,
              const float* __restrict__ bias,
              const float* __restrict__ add1, const float* __restrict__ add2,
              __nv_bfloat16* __restrict__ Ch, __nv_bfloat16* __restrict__ Cl)
{
    extern __shared__ char smem[];
    const uint32_t sbase = smem_u32(smem);
    const int tid = threadIdx.x, lane = tid & 31, wid = tid >> 5;
    const int warpM = wid >> 1, warpN = wid & 1;           // 4 x 2 warps
    const long m0 = (long)blockIdx.x * 128;
    const long n0 = (long)blockIdx.y * 128;

    float acc[2][8][4];
    #pragma unroll
    for (int i = 0; i < 2; i++)
        #pragma unroll
        for (int j = 0; j < 8; j++)
            #pragma unroll
            for (int q = 0; q < 4; q++) acc[i][j][q] = 0.f;

    const __nv_bfloat16* gbase0 = Ah + m0 * lda;
    const __nv_bfloat16* gbase1 = Al + m0 * lda;
    const __nv_bfloat16* gbase2 = Bh + n0 * ldb;
    const __nv_bfloat16* gbase3 = Bl + n0 * ldb;

    const int nch = K >> 5;                                 // K / 32

    // ---- stage loader ----
    #define LOAD_STAGE(CH, S) do {                                             \
        const long k0_ = (long)(CH) << 5;                                      \
        const uint32_t so_ = sbase + (S) * STAGE_B;                            \
        _Pragma("unroll")                                                      \
        for (int i_ = 0; i_ < 8; i_++) {                                       \
            int mat_ = i_ >> 1;                                                \
            int idx_ = ((i_ & 1) << 8) + tid;                                  \
            int row_ = idx_ >> 2, c16_ = idx_ & 3;                             \
            uint32_t dst_ = so_ + mat_ * MAT_B + row_ * (AST * 2) + c16_ * 16; \
            const __nv_bfloat16* src_;                                         \
            if      (mat_ == 0) src_ = gbase0 + (long)row_ * lda + k0_ + c16_ * 8; \
            else if (mat_ == 1) src_ = gbase1 + (long)row_ * lda + k0_ + c16_ * 8; \
            else if (mat_ == 2) src_ = gbase2 + (long)row_ * ldb + k0_ + c16_ * 8; \
            else                src_ = gbase3 + (long)row_ * ldb + k0_ + c16_ * 8; \
            CP_ASYNC16(dst_, src_);                                            \
        }                                                                      \
    } while (0)

    LOAD_STAGE(0, 0);
    CP_COMMIT();

    const int subA = ((lane >> 3) & 1) * 8;     // row offset within m16
    const int subAk = ((lane >> 4)) * 8;        // k offset
    const int subBr = ((lane >> 4)) * 8;        // row (n) offset within n16
    const int subBk = ((lane >> 3) & 1) * 8;    // k offset
    const int li = lane & 7;

    for (int ch = 0; ch < nch; ch++) {
        if (ch + 1 < nch) LOAD_STAGE(ch + 1, (ch + 1) & 1);
        CP_COMMIT();
        CP_WAIT1();
        __syncthreads();

        const uint32_t so = sbase + (ch & 1) * STAGE_B;
        const uint32_t sA_h = so;
        const uint32_t sA_l = so + MAT_B;
        const uint32_t sB_h = so + 2 * MAT_B;
        const uint32_t sB_l = so + 3 * MAT_B;

        #pragma unroll
        for (int ks = 0; ks < 2; ks++) {
            const int kk = ks * 16;
            uint32_t a[2][4], bb[4][4];

            // B hi fragments (n64 = 4 pairs of n8 tiles)
            #pragma unroll
            for (int p = 0; p < 4; p++) {
                int r = warpN * 64 + p * 16 + subBr + li;
                int c = kk + subBk;
                LDMX4(bb[p][0], bb[p][1], bb[p][2], bb[p][3],
                      sB_h + (uint32_t)(r * (AST * 2) + c * 2));
            }
            // A hi
            #pragma unroll
            for (int mt = 0; mt < 2; mt++) {
                int r = warpM * 32 + mt * 16 + subA + li;
                int c = kk + subAk;
                LDMX4(a[mt][0], a[mt][1], a[mt][2], a[mt][3],
                      sA_h + (uint32_t)(r * (AST * 2) + c * 2));
            }
            #pragma unroll
            for (int mt = 0; mt < 2; mt++)
                #pragma unroll
                for (int nt = 0; nt < 8; nt++)
                    MMA_BF16(acc[mt][nt][0], acc[mt][nt][1], acc[mt][nt][2], acc[mt][nt][3],
                             a[mt][0], a[mt][1], a[mt][2], a[mt][3],
                             bb[nt >> 1][(nt & 1) * 2], bb[nt >> 1][(nt & 1) * 2 + 1]);
            // A lo (reuse B hi)
            #pragma unroll
            for (int mt = 0; mt < 2; mt++) {
                int r = warpM * 32 + mt * 16 + subA + li;
                int c = kk + subAk;
                LDMX4(a[mt][0], a[mt][1], a[mt][2], a[mt][3],
                      sA_l + (uint32_t)(r * (AST * 2) + c * 2));
            }
            #pragma unroll
            for (int mt = 0; mt < 2; mt++)
                #pragma unroll
                for (int nt = 0; nt < 8; nt++)
                    MMA_BF16(acc[mt][nt][0], acc[mt][nt][1], acc[mt][nt][2], acc[mt][nt][3],
                             a[mt][0], a[mt][1], a[mt][2], a[mt][3],
                             bb[nt >> 1][(nt & 1) * 2], bb[nt >> 1][(nt & 1) * 2 + 1]);
            // B lo + A hi
            #pragma unroll
            for (int p = 0; p < 4; p++) {
                int r = warpN * 64 + p * 16 + subBr + li;
                int c = kk + subBk;
                LDMX4(bb[p][0], bb[p][1], bb[p][2], bb[p][3],
                      sB_l + (uint32_t)(r * (AST * 2) + c * 2));
            }
            #pragma unroll
            for (int mt = 0; mt < 2; mt++) {
                int r = warpM * 32 + mt * 16 + subA + li;
                int c = kk + subAk;
                LDMX4(a[mt][0], a[mt][1], a[mt][2], a[mt][3],
                      sA_h + (uint32_t)(r * (AST * 2) + c * 2));
            }
            #pragma unroll
            for (int mt = 0; mt < 2; mt++)
                #pragma unroll
                for (int nt = 0; nt < 8; nt++)
                    MMA_BF16(acc[mt][nt][0], acc[mt][nt][1], acc[mt][nt][2], acc[mt][nt][3],
                             a[mt][0], a[mt][1], a[mt][2], a[mt][3],
                             bb[nt >> 1][(nt & 1) * 2], bb[nt >> 1][(nt & 1) * 2 + 1]);
        }
        __syncthreads();
    }

    // ---- epilogue ----
    const int qrow = lane >> 2;
    const int qcol = (lane & 3) * 2;
    #pragma unroll
    for (int mt = 0; mt < 2; mt++) {
        #pragma unroll
        for (int half = 0; half < 2; half++) {       // c0,c1 vs c2,c3
            long m = m0 + warpM * 32 + mt * 16 + qrow + half * 8;
            #pragma unroll
            for (int nt = 0; nt < 8; nt++) {
                long n = n0 + warpN * 64 + nt * 8 + qcol;
                float v0 = acc[mt][nt][half * 2];
                float v1 = acc[mt][nt][half * 2 + 1];
                if (mode == 0) {
                    float2 o = {v0, v1};
                    *(float2*)(C + m * ldc + n) = o;
                } else if (mode == 2) {
                    v0 = gelu_f(v0 + bias[n]);
                    v1 = gelu_f(v1 + bias[n + 1]);
                    __nv_bfloat16 h0 = __float2bfloat16(v0);
                    __nv_bfloat16 h1 = __float2bfloat16(v1);
                    uint32_t ph = ((uint32_t)__bfloat16_as_ushort(h1) << 16) | __bfloat16_as_ushort(h0);
                    __nv_bfloat16 l0 = __float2bfloat16(v0 - __bfloat162float(h0));
                    __nv_bfloat16 l1 = __float2bfloat16(v1 - __bfloat162float(h1));
                    uint32_t pl = ((uint32_t)__bfloat16_as_ushort(l1) << 16) | __bfloat16_as_ushort(l0);
                    *(uint32_t*)(Ch + m * ldc + n) = ph;
                    *(uint32_t*)(Cl + m * ldc + n) = pl;
                } else {
                    float2 bv = *(const float2*)(bias + n);
                    float2 a1 = *(const float2*)(add1 + m * ldc + n);
                    float2 a2 = *(const float2*)(add2 + m * ldc + n);
                    float2 o = {v0 + bv.x + a1.x + a2.x, v1 + bv.y + a1.y + a2.y};
                    *(float2*)(C + m * ldc + n) = o;
                }
            }
        }
    }
}

// ==================== launch ====================
extern "C" void kernel_launch(void* const* d_in, const int* in_sizes, int n_in,
                              void* d_out, int out_size)
{
    const int*   positions = (const int*)  d_in[0];
    const float* hidden    = (const float*)d_in[1];
    const float* ln_g      = (const float*)d_in[2];
    const float* ln_b      = (const float*)d_in[3];
    const float* w_qkv     = (const float*)d_in[4];
    const float* w_out     = (const float*)d_in[5];
    const float* w_fc_in   = (const float*)d_in[6];
    const float* b_fc_in   = (const float*)d_in[7];
    const float* w_fc_out  = (const float*)d_in[8];
    const float* b_fc_out  = (const float*)d_in[9];
    float* out = (float*)d_out;

    float *qkv, *scores, *ctx, *attn, *kT;
    __nv_bfloat16 *lnh, *lnl, *ctxh, *ctxl, *mlphh, *mlphl;
    __nv_bfloat16 *wqkvTh, *wqkvTl, *woutTh, *woutTl, *wfiTh, *wfiTl, *wfoTh, *wfoTl;
    cudaGetSymbolAddress((void**)&qkv,    g_qkv);
    cudaGetSymbolAddress((void**)&scores, g_scores);
    cudaGetSymbolAddress((void**)&ctx,    g_ctx);
    cudaGetSymbolAddress((void**)&attn,   g_attn);
    cudaGetSymbolAddress((void**)&kT,     g_kT);
    cudaGetSymbolAddress((void**)&lnh,    g_ln_h);
    cudaGetSymbolAddress((void**)&lnl,    g_ln_l);
    cudaGetSymbolAddress((void**)&ctxh,   g_ctx_h);
    cudaGetSymbolAddress((void**)&ctxl,   g_ctx_l);
    cudaGetSymbolAddress((void**)&mlphh,  g_mlph_h);
    cudaGetSymbolAddress((void**)&mlphl,  g_mlph_l);
    cudaGetSymbolAddress((void**)&wqkvTh, g_wqkvT_h);
    cudaGetSymbolAddress((void**)&wqkvTl, g_wqkvT_l);
    cudaGetSymbolAddress((void**)&woutTh, g_woutT_h);
    cudaGetSymbolAddress((void**)&woutTl, g_woutT_l);
    cudaGetSymbolAddress((void**)&wfiTh,  g_wfiT_h);
    cudaGetSymbolAddress((void**)&wfiTl,  g_wfiT_l);
    cudaGetSymbolAddress((void**)&wfoTh,  g_wfoT_h);
    cudaGetSymbolAddress((void**)&wfoTl,  g_wfoT_l);

    cudaFuncSetAttribute(gemm_mma, cudaFuncAttributeMaxDynamicSharedMemorySize, 2 * STAGE_B);
    const int GS = 2 * STAGE_B;

    dim3 tb(32, 8);

    // weight transpose + split
    wconv_kernel<<<dim3(3 * DM_ / 32, DM_ / 32),  tb>>>(w_qkv,    DM_,  3 * DM_, wqkvTh, wqkvTl);
    wconv_kernel<<<dim3(DM_ / 32,     DM_ / 32),  tb>>>(w_out,    DM_,  DM_,     woutTh, woutTl);
    wconv_kernel<<<dim3(DFF_ / 32,    DM_ / 32),  tb>>>(w_fc_in,  DM_,  DFF_,    wfiTh,  wfiTl);
    wconv_kernel<<<dim3(DM_ / 32,     DFF_ / 32), tb>>>(w_fc_out, DFF_, DM_,     wfoTh,  wfoTl);

    // 1. LayerNorm -> bf16 hi/lo
    ln_kernel<<<T_, 256>>>(hidden, ln_g, ln_b, lnh, lnl);

    // 2. QKV = ln @ w_qkv (tensor, fp32 out)
    gemm_mma<<<dim3(T_ / 128, 3 * DM_ / 128), 256, GS>>>(
        lnh, lnl, DM_, wqkvTh, wqkvTl, DM_,
        qkv, 3 * DM_, DM_, 0, nullptr, nullptr, nullptr, nullptr, nullptr);

    // 3. RoPE
    rope_kernel<<<dim3(2 * H_, T_), 32>>>(qkv, positions);

    // 4. per-head k transpose
    ktrans_kernel<<<dim3(T_ / 32, HD_ / 32, H_), tb>>>(qkv, kT);

    // 5. scores = q @ kT, scale + causal mask (fp32)
    sgemm_kernel<<<dim3(T_ / BN, T_ / BM, H_), 256>>>(
        qkv, 3 * DM_, HD_,
        kT, T_, 1, (long)HD_ * T_,
        scores, T_, (long)T_ * T_,
        T_, T_, HD_, 1, 0.0625f);

    // 6. softmax
    softmax_kernel<<<H_ * T_, 256>>>(scores);

    // 7. ctx = probs @ v (fp32)
    sgemm_kernel<<<dim3(HD_ / BN, T_ / BM, H_), 256>>>(
        scores, T_, (long)T_ * T_,
        qkv + 2 * DM_, 3 * DM_, 1, HD_,
        ctx, DM_, HD_,
        T_, HD_, T_, 0, 0.f);

    // 8. split ctx -> bf16 hi/lo
    split_kernel<<<(T_ * DM_ / 4 + 255) / 256, 256>>>(ctx, ctxh, ctxl, (long)T_ * DM_ / 4);

    // 9. attn = ctx @ w_out (tensor, fp32 out)
    gemm_mma<<<dim3(T_ / 128, DM_ / 128), 256, GS>>>(
        ctxh, ctxl, DM_, woutTh, woutTl, DM_,
        attn, DM_, DM_, 0, nullptr, nullptr, nullptr, nullptr, nullptr);

    // 10. mlph = gelu(ln @ w_fc_in + b) (tensor, bf16 hi/lo out)
    gemm_mma<<<dim3(T_ / 128, DFF_ / 128), 256, GS>>>(
        lnh, lnl, DM_, wfiTh, wfiTl, DM_,
        nullptr, DFF_, DM_, 2, b_fc_in, nullptr, nullptr, mlphh, mlphl);

    // 11. out = mlph @ w_fc_out + b + attn + residual (tensor)
    gemm_mma<<<dim3(T_ / 128, DM_ / 128), 256, GS>>>(
        mlphh, mlphl, DFF_, wfoTh, wfoTl, DFF_,
        out, DM_, DFF_, 3, b_fc_out, attn, hidden, nullptr, nullptr);
}

// round 5
// speedup vs baseline: 3.4998x; 1.2870x over previous
#include <cuda_runtime.h>
#include <cuda_bf16.h>
#include <math.h>
#include <stdint.h>

#define T_   2048
#define DM_  4096
#define H_   16
#define HD_  256
#define RD_  64
#define DFF_ 16384
#define EPS_ 1e-5f

// ==================== scratch (__device__ globals, no allocs) ====================
__device__ float g_qkv   [(long)T_ * 3 * DM_];
__device__ float g_scores[(long)H_ * T_ * T_];
__device__ float g_attn  [(long)T_ * DM_];
// split activations (bf16 hi/lo)
__device__ __nv_bfloat16 g_ln_h  [(long)T_ * DM_];
__device__ __nv_bfloat16 g_ln_l  [(long)T_ * DM_];
__device__ __nv_bfloat16 g_q_h   [(long)T_ * DM_];
__device__ __nv_bfloat16 g_q_l   [(long)T_ * DM_];
__device__ __nv_bfloat16 g_k_h   [(long)T_ * DM_];
__device__ __nv_bfloat16 g_k_l   [(long)T_ * DM_];
__device__ __nv_bfloat16 g_vT_h  [(long)H_ * HD_ * T_];
__device__ __nv_bfloat16 g_vT_l  [(long)H_ * HD_ * T_];
__device__ __nv_bfloat16 g_pr_h  [(long)H_ * T_ * T_];
__device__ __nv_bfloat16 g_pr_l  [(long)H_ * T_ * T_];
__device__ __nv_bfloat16 g_ctx_h [(long)T_ * DM_];
__device__ __nv_bfloat16 g_ctx_l [(long)T_ * DM_];
__device__ __nv_bfloat16 g_mlph_h[(long)T_ * DFF_];
__device__ __nv_bfloat16 g_mlph_l[(long)T_ * DFF_];
// transposed + split weights: [N][K] bf16
__device__ __nv_bfloat16 g_wqkvT_h[(long)3 * DM_ * DM_];
__device__ __nv_bfloat16 g_wqkvT_l[(long)3 * DM_ * DM_];
__device__ __nv_bfloat16 g_woutT_h[(long)DM_ * DM_];
__device__ __nv_bfloat16 g_woutT_l[(long)DM_ * DM_];
__device__ __nv_bfloat16 g_wfiT_h [(long)DFF_ * DM_];
__device__ __nv_bfloat16 g_wfiT_l [(long)DFF_ * DM_];
__device__ __nv_bfloat16 g_wfoT_h [(long)DM_ * DFF_];
__device__ __nv_bfloat16 g_wfoT_l [(long)DM_ * DFF_];

// ==================== helpers ====================
__device__ __forceinline__ uint32_t smem_u32(const void* p) {
    uint32_t a;
    asm("{ .reg .u64 t; cvta.to.shared.u64 t, %1; cvt.u32.u64 %0, t; }" : "=r"(a) : "l"(p));
    return a;
}
#define CP_ASYNC16(dst, src) \
    asm volatile("cp.async.cg.shared.global [%0], [%1], 16;" :: "r"(dst), "l"(src) : "memory")
#define CP_COMMIT() asm volatile("cp.async.commit_group;" ::: "memory")
#define CP_WAIT1()  asm volatile("cp.async.wait_group 1;" ::: "memory")
#define LDMX4(r0, r1, r2, r3, addr) \
    asm volatile("ldmatrix.sync.aligned.m8n8.x4.shared.b16 {%0,%1,%2,%3}, [%4];" \
        : "=r"(r0), "=r"(r1), "=r"(r2), "=r"(r3) : "r"(addr))
#define MMA_BF16(c0, c1, c2, c3, a0, a1, a2, a3, b0, b1) \
    asm volatile("mma.sync.aligned.m16n8k16.row.col.f32.bf16.bf16.f32 " \
        "{%0,%1,%2,%3}, {%4,%5,%6,%7}, {%8,%9}, {%0,%1,%2,%3};" \
        : "+f"(c0), "+f"(c1), "+f"(c2), "+f"(c3) \
        : "r"(a0), "r"(a1), "r"(a2), "r"(a3), "r"(b0), "r"(b1))

__device__ __forceinline__ float gelu_f(float v) {
    return 0.5f * v * (1.0f + tanhf(0.7978845608028654f * (v + 0.044715f * v * v * v)));
}
__device__ __forceinline__ uint32_t pack_hi(float a, float b, uint32_t& lo) {
    __nv_bfloat16 h0 = __float2bfloat16(a);
    __nv_bfloat16 h1 = __float2bfloat16(b);
    __nv_bfloat16 l0 = __float2bfloat16(a - __bfloat162float(h0));
    __nv_bfloat16 l1 = __float2bfloat16(b - __bfloat162float(h1));
    lo = ((uint32_t)__bfloat16_as_ushort(l1) << 16) | __bfloat16_as_ushort(l0);
    return ((uint32_t)__bfloat16_as_ushort(h1) << 16) | __bfloat16_as_ushort(h0);
}

// ==================== LayerNorm -> bf16 hi/lo split ====================
__global__ void ln_kernel(const float* __restrict__ x, const float* __restrict__ g,
                          const float* __restrict__ b,
                          __nv_bfloat16* __restrict__ oh, __nv_bfloat16* __restrict__ ol)
{
    int row = blockIdx.x;
    const float* xr = x + (long)row * DM_;
    int tid = threadIdx.x;
    float s = 0.f, s2 = 0.f;
    #pragma unroll 4
    for (int i = tid; i < DM_; i += 256) { float v = xr[i]; s += v; s2 += v * v; }
    for (int o = 16; o > 0; o >>= 1) {
        s  += __shfl_xor_sync(0xffffffff, s,  o);
        s2 += __shfl_xor_sync(0xffffffff, s2, o);
    }
    __shared__ float ws[8], ws2[8];
    int wid = tid >> 5, lid = tid & 31;
    if (lid == 0) { ws[wid] = s; ws2[wid] = s2; }
    __syncthreads();
    if (wid == 0) {
        s  = (lid < 8) ? ws[lid]  : 0.f;
        s2 = (lid < 8) ? ws2[lid] : 0.f;
        for (int o = 4; o > 0; o >>= 1) {
            s  += __shfl_xor_sync(0xffffffff, s,  o);
            s2 += __shfl_xor_sync(0xffffffff, s2, o);
        }
        if (lid == 0) { ws[0] = s; ws2[0] = s2; }
    }
    __syncthreads();
    float mu  = ws[0]  * (1.0f / DM_);
    float var = ws2[0] * (1.0f / DM_) - mu * mu;
    float rs  = rsqrtf(var + EPS_);
    #pragma unroll 4
    for (int i = tid; i < DM_; i += 256) {
        float y = (xr[i] - mu) * rs * g[i] + b[i];
        __nv_bfloat16 h = __float2bfloat16(y);
        oh[(long)row * DM_ + i] = h;
        ol[(long)row * DM_ + i] = __float2bfloat16(y - __bfloat162float(h));
    }
}

// ==================== weight transpose + bf16 split:  W[K,N] -> Th/Tl[N,K] ====================
__global__ void wconv_kernel(const float* __restrict__ W, int K, int N,
                             __nv_bfloat16* __restrict__ Th, __nv_bfloat16* __restrict__ Tl)
{
    __shared__ float tile[32][33];
    int n0 = blockIdx.x * 32, k0 = blockIdx.y * 32;
    int tx = threadIdx.x, ty = threadIdx.y;       // 32 x 8
    #pragma unroll
    for (int i = 0; i < 4; i++)
        tile[ty + 8 * i][tx] = W[(long)(k0 + ty + 8 * i) * N + n0 + tx];
    __syncthreads();
    #pragma unroll
    for (int i = 0; i < 4; i++) {
        float v = tile[tx][ty + 8 * i];
        __nv_bfloat16 h = __float2bfloat16(v);
        __nv_bfloat16 l = __float2bfloat16(v - __bfloat162float(h));
        long o = (long)(n0 + ty + 8 * i) * K + k0 + tx;
        Th[o] = h; Tl[o] = l;
    }
}

// ==================== RoPE + split q,k -> bf16 hi/lo [T][DM] ====================
__global__ void rope_split_kernel(const float* __restrict__ qkv, const int* __restrict__ pos,
                                  __nv_bfloat16* __restrict__ qh, __nv_bfloat16* __restrict__ ql,
                                  __nv_bfloat16* __restrict__ kh, __nv_bfloat16* __restrict__ kl)
{
    int t = blockIdx.x;
    int tid = threadIdx.x;                         // 256
    const float* qrow = qkv + (long)t * (3 * DM_);
    const float* krow = qrow + DM_;
    float p = (float)pos[t];
    #pragma unroll
    for (int it = 0; it < 8; it++) {
        int pr = it * 256 + tid;                   // pair index 0..2047
        int h  = pr >> 7;
        int d2 = pr & 127;
        int base = h * HD_ + 2 * d2;
        float q1 = qrow[base], q2 = qrow[base + 1];
        float k1 = krow[base], k2 = krow[base + 1];
        if (d2 < RD_ / 2) {
            float freq = powf(10000.0f, -(float)d2 / (RD_ / 2));
            float sn, cs; sincosf(p * freq, &sn, &cs);
            float a = q1 * cs - q2 * sn, bq = q2 * cs + q1 * sn; q1 = a; q2 = bq;
            a = k1 * cs - k2 * sn; float bk = k2 * cs + k1 * sn; k1 = a; k2 = bk;
        }
        long o = ((long)t * DM_ + base) >> 1;      // u32 index
        uint32_t lo;
        ((uint32_t*)qh)[o] = pack_hi(q1, q2, lo); ((uint32_t*)ql)[o] = lo;
        ((uint32_t*)kh)[o] = pack_hi(k1, k2, lo); ((uint32_t*)kl)[o] = lo;
    }
}

// ==================== v transpose + split: vT[h][d][t] bf16 hi/lo ====================
__global__ void vtrans_split_kernel(const float* __restrict__ qkv,
                                    __nv_bfloat16* __restrict__ vTh, __nv_bfloat16* __restrict__ vTl)
{
    __shared__ float tile[32][33];
    int h = blockIdx.z;
    int t0 = blockIdx.x * 32, d0 = blockIdx.y * 32;
    int tx = threadIdx.x, ty = threadIdx.y;
    #pragma unroll
    for (int i = 0; i < 4; i++)
        tile[ty + 8 * i][tx] = qkv[(long)(t0 + ty + 8 * i) * (3 * DM_) + 2 * DM_ + h * HD_ + d0 + tx];
    __syncthreads();
    #pragma unroll
    for (int i = 0; i < 4; i++) {
        float v = tile[tx][ty + 8 * i];
        __nv_bfloat16 hh = __float2bfloat16(v);
        long o = ((long)h * HD_ + d0 + ty + 8 * i) * T_ + t0 + tx;
        vTh[o] = hh;
        vTl[o] = __float2bfloat16(v - __bfloat162float(hh));
    }
}

// ==================== causal softmax: fp32 scores -> bf16 hi/lo probs ====================
__global__ void softmax_kernel(const float* __restrict__ scores,
                               __nv_bfloat16* __restrict__ ph, __nv_bfloat16* __restrict__ pl)
{
    long row = blockIdx.x;                 // h*T + t
    int t = (int)(row & (T_ - 1));
    int len = t + 1;
    const float* p = scores + row * T_;
    int tid = threadIdx.x;
    float mx = -3.4e38f;
    for (int i = tid; i < len; i += 256) mx = fmaxf(mx, p[i]);
    for (int o = 16; o > 0; o >>= 1) mx = fmaxf(mx, __shfl_xor_sync(0xffffffff, mx, o));
    __shared__ float sm[8];
    int wid = tid >> 5, lid = tid & 31;
    if (lid == 0) sm[wid] = mx;
    __syncthreads();
    if (tid < 8) {
        mx = sm[tid];
        for (int o = 4; o > 0; o >>= 1) mx = fmaxf(mx, __shfl_xor_sync(0xff, mx, o));
        if (tid == 0) sm[0] = mx;
    }
    __syncthreads();
    mx = sm[0];
    float sum = 0.f;
    for (int i = tid; i < len; i += 256) sum += __expf(p[i] - mx);
    for (int o = 16; o > 0; o >>= 1) sum += __shfl_xor_sync(0xffffffff, sum, o);
    __shared__ float ss[8];
    if (lid == 0) ss[wid] = sum;
    __syncthreads();
    if (tid < 8) {
        sum = ss[tid];
        for (int o = 4; o > 0; o >>= 1) sum += __shfl_xor_sync(0xff, sum, o);
        if (tid == 0) ss[0] = sum;
    }
    __syncthreads();
    float inv = 1.0f / ss[0];
    for (int i = tid; i < T_; i += 256) {
        float e = (i < len) ? __expf(p[i] - mx) * inv : 0.f;
        __nv_bfloat16 hh = __float2bfloat16(e);
        ph[row * T_ + i] = hh;
        pl[row * T_ + i] = __float2bfloat16(e - __bfloat162float(hh));
    }
}

// ==================== bf16-split mma.sync GEMM (batched by blockIdx.z) ====================
// C = (Ah+Al) @ (Bh+Bl)^T.  A[M][K] hi/lo, B[N][K] hi/lo, fp32 acc; 3 passes.
// mode 0: fp32 C                       mode 1: v*scale -> fp32 C, skip tiles above causal diag
// mode 2: gelu(v + bias[n]) -> hi/lo   mode 3: v + bias[n] + add1 + add2 -> fp32 C
// mode 4: plain -> hi/lo
#define AST 40   // smem row stride in bf16 elems (80 bytes, conflict-free ldmatrix)
#define STAGE_B 40960
#define MAT_B   10240

__global__ __launch_bounds__(256, 2)
void gemm_mma(const __nv_bfloat16* __restrict__ Ah, const __nv_bfloat16* __restrict__ Al,
              long lda, long hsA,
              const __nv_bfloat16* __restrict__ Bh, const __nv_bfloat16* __restrict__ Bl,
              long ldb, long hsB,
              float* __restrict__ C, long ldc, long hsC, int K, int mode, float scale,
              const float* __restrict__ bias,
              const float* __restrict__ add1, const float* __restrict__ add2,
              __nv_bfloat16* __restrict__ Ch, __nv_bfloat16* __restrict__ Cl)
{
    if (mode == 1 && blockIdx.y > blockIdx.x) return;   // fully-masked causal tile

    extern __shared__ char smem[];
    const uint32_t sbase = smem_u32(smem);
    const int tid = threadIdx.x, lane = tid & 31, wid = tid >> 5;
    const int warpM = wid >> 1, warpN = wid & 1;        // 4 x 2 warps
    const long m0 = (long)blockIdx.x * 128;
    const long n0 = (long)blockIdx.y * 128;
    const long z  = blockIdx.z;

    float acc[2][8][4];
    #pragma unroll
    for (int i = 0; i < 2; i++)
        #pragma unroll
        for (int j = 0; j < 8; j++)
            #pragma unroll
            for (int q = 0; q < 4; q++) acc[i][j][q] = 0.f;

    const __nv_bfloat16* gbase0 = Ah + z * hsA + m0 * lda;
    const __nv_bfloat16* gbase1 = Al + z * hsA + m0 * lda;
    const __nv_bfloat16* gbase2 = Bh + z * hsB + n0 * ldb;
    const __nv_bfloat16* gbase3 = Bl + z * hsB + n0 * ldb;

    const int nch = K >> 5;                              // K / 32

    #define LOAD_STAGE(CH, S) do {                                             \
        const long k0_ = (long)(CH) << 5;                                      \
        const uint32_t so_ = sbase + (S) * STAGE_B;                            \
        _Pragma("unroll")                                                      \
        for (int i_ = 0; i_ < 8; i_++) {                                       \
            int mat_ = i_ >> 1;                                                \
            int idx_ = ((i_ & 1) << 8) + tid;                                  \
            int row_ = idx_ >> 2, c16_ = idx_ & 3;                             \
            uint32_t dst_ = so_ + mat_ * MAT_B + row_ * (AST * 2) + c16_ * 16; \
            const __nv_bfloat16* src_;                                         \
            if      (mat_ == 0) src_ = gbase0 + (long)row_ * lda + k0_ + c16_ * 8; \
            else if (mat_ == 1) src_ = gbase1 + (long)row_ * lda + k0_ + c16_ * 8; \
            else if (mat_ == 2) src_ = gbase2 + (long)row_ * ldb + k0_ + c16_ * 8; \
            else                src_ = gbase3 + (long)row_ * ldb + k0_ + c16_ * 8; \
            CP_ASYNC16(dst_, src_);                                            \
        }                                                                      \
    } while (0)

    LOAD_STAGE(0, 0);
    CP_COMMIT();

    const int subA  = ((lane >> 3) & 1) * 8;
    const int subAk = ((lane >> 4)) * 8;
    const int subBr = ((lane >> 4)) * 8;
    const int subBk = ((lane >> 3) & 1) * 8;
    const int li = lane & 7;

    for (int ch = 0; ch < nch; ch++) {
        if (ch + 1 < nch) LOAD_STAGE(ch + 1, (ch + 1) & 1);
        CP_COMMIT();
        CP_WAIT1();
        __syncthreads();

        const uint32_t so = sbase + (ch & 1) * STAGE_B;
        const uint32_t sA_h = so;
        const uint32_t sA_l = so + MAT_B;
        const uint32_t sB_h = so + 2 * MAT_B;
        const uint32_t sB_l = so + 3 * MAT_B;

        #pragma unroll
        for (int ks = 0; ks < 2; ks++) {
            const int kk = ks * 16;
            uint32_t a[2][4], bb[4][4];

            #pragma unroll
            for (int p = 0; p < 4; p++) {
                int r = warpN * 64 + p * 16 + subBr + li;
                int c = kk + subBk;
                LDMX4(bb[p][0], bb[p][1], bb[p][2], bb[p][3],
                      sB_h + (uint32_t)(r * (AST * 2) + c * 2));
            }
            #pragma unroll
            for (int mt = 0; mt < 2; mt++) {
                int r = warpM * 32 + mt * 16 + subA + li;
                int c = kk + subAk;
                LDMX4(a[mt][0], a[mt][1], a[mt][2], a[mt][3],
                      sA_h + (uint32_t)(r * (AST * 2) + c * 2));
            }
            #pragma unroll
            for (int mt = 0; mt < 2; mt++)
                #pragma unroll
                for (int nt = 0; nt < 8; nt++)
                    MMA_BF16(acc[mt][nt][0], acc[mt][nt][1], acc[mt][nt][2], acc[mt][nt][3],
                             a[mt][0], a[mt][1], a[mt][2], a[mt][3],
                             bb[nt >> 1][(nt & 1) * 2], bb[nt >> 1][(nt & 1) * 2 + 1]);
            #pragma unroll
            for (int mt = 0; mt < 2; mt++) {
                int r = warpM * 32 + mt * 16 + subA + li;
                int c = kk + subAk;
                LDMX4(a[mt][0], a[mt][1], a[mt][2], a[mt][3],
                      sA_l + (uint32_t)(r * (AST * 2) + c * 2));
            }
            #pragma unroll
            for (int mt = 0; mt < 2; mt++)
                #pragma unroll
                for (int nt = 0; nt < 8; nt++)
                    MMA_BF16(acc[mt][nt][0], acc[mt][nt][1], acc[mt][nt][2], acc[mt][nt][3],
                             a[mt][0], a[mt][1], a[mt][2], a[mt][3],
                             bb[nt >> 1][(nt & 1) * 2], bb[nt >> 1][(nt & 1) * 2 + 1]);
            #pragma unroll
            for (int p = 0; p < 4; p++) {
                int r = warpN * 64 + p * 16 + subBr + li;
                int c = kk + subBk;
                LDMX4(bb[p][0], bb[p][1], bb[p][2], bb[p][3],
                      sB_l + (uint32_t)(r * (AST * 2) + c * 2));
            }
            #pragma unroll
            for (int mt = 0; mt < 2; mt++) {
                int r = warpM * 32 + mt * 16 + subA + li;
                int c = kk + subAk;
                LDMX4(a[mt][0], a[mt][1], a[mt][2], a[mt][3],
                      sA_h + (uint32_t)(r * (AST * 2) + c * 2));
            }
            #pragma unroll
            for (int mt = 0; mt < 2; mt++)
                #pragma unroll
                for (int nt = 0; nt < 8; nt++)
                    MMA_BF16(acc[mt][nt][0], acc[mt][nt][1], acc[mt][nt][2], acc[mt][nt][3],
                             a[mt][0], a[mt][1], a[mt][2], a[mt][3],
                             bb[nt >> 1][(nt & 1) * 2], bb[nt >> 1][(nt & 1) * 2 + 1]);
        }
        __syncthreads();
    }

    // ---- epilogue ----
    if (C)  C  += z * hsC;
    if (Ch) { Ch += z * hsC; Cl += z * hsC; }
    const int qrow = lane >> 2;
    const int qcol = (lane & 3) * 2;
    #pragma unroll
    for (int mt = 0; mt < 2; mt++) {
        #pragma unroll
        for (int half = 0; half < 2; half++) {
            long m = m0 + warpM * 32 + mt * 16 + qrow + half * 8;
            #pragma unroll
            for (int nt = 0; nt < 8; nt++) {
                long n = n0 + warpN * 64 + nt * 8 + qcol;
                float v0 = acc[mt][nt][half * 2];
                float v1 = acc[mt][nt][half * 2 + 1];
                if (mode == 0) {
                    float2 o = {v0, v1};
                    *(float2*)(C + m * ldc + n) = o;
                } else if (mode == 1) {
                    float2 o = {v0 * scale, v1 * scale};
                    *(float2*)(C + m * ldc + n) = o;
                } else if (mode == 2) {
                    v0 = gelu_f(v0 + bias[n]);
                    v1 = gelu_f(v1 + bias[n + 1]);
                    uint32_t pl;
                    uint32_t ph = pack_hi(v0, v1, pl);
                    *(uint32_t*)(Ch + m * ldc + n) = ph;
                    *(uint32_t*)(Cl + m * ldc + n) = pl;
                } else if (mode == 3) {
                    float2 bv = *(const float2*)(bias + n);
                    float2 a1 = *(const float2*)(add1 + m * ldc + n);
                    float2 a2 = *(const float2*)(add2 + m * ldc + n);
                    float2 o = {v0 + bv.x + a1.x + a2.x, v1 + bv.y + a1.y + a2.y};
                    *(float2*)(C + m * ldc + n) = o;
                } else {
                    uint32_t pl;
                    uint32_t ph = pack_hi(v0, v1, pl);
                    *(uint32_t*)(Ch + m * ldc + n) = ph;
                    *(uint32_t*)(Cl + m * ldc + n) = pl;
                }
            }
        }
    }
}

// ==================== launch ====================
extern "C" void kernel_launch(void* const* d_in, const int* in_sizes, int n_in,
                              void* d_out, int out_size)
{
    const int*   positions = (const int*)  d_in[0];
    const float* hidden    = (const float*)d_in[1];
    const float* ln_g      = (const float*)d_in[2];
    const float* ln_b      = (const float*)d_in[3];
    const float* w_qkv     = (const float*)d_in[4];
    const float* w_out     = (const float*)d_in[5];
    const float* w_fc_in   = (const float*)d_in[6];
    const float* b_fc_in   = (const float*)d_in[7];
    const float* w_fc_out  = (const float*)d_in[8];
    const float* b_fc_out  = (const float*)d_in[9];
    float* out = (float*)d_out;

    float *qkv, *scores, *attn;
    __nv_bfloat16 *lnh, *lnl, *qh, *ql, *kh, *kl, *vTh, *vTl, *prh, *prl, *ctxh, *ctxl, *mlphh, *mlphl;
    __nv_bfloat16 *wqkvTh, *wqkvTl, *woutTh, *woutTl, *wfiTh, *wfiTl, *wfoTh, *wfoTl;
    cudaGetSymbolAddress((void**)&qkv,    g_qkv);
    cudaGetSymbolAddress((void**)&scores, g_scores);
    cudaGetSymbolAddress((void**)&attn,   g_attn);
    cudaGetSymbolAddress((void**)&lnh,    g_ln_h);
    cudaGetSymbolAddress((void**)&lnl,    g_ln_l);
    cudaGetSymbolAddress((void**)&qh,     g_q_h);
    cudaGetSymbolAddress((void**)&ql,     g_q_l);
    cudaGetSymbolAddress((void**)&kh,     g_k_h);
    cudaGetSymbolAddress((void**)&kl,     g_k_l);
    cudaGetSymbolAddress((void**)&vTh,    g_vT_h);
    cudaGetSymbolAddress((void**)&vTl,    g_vT_l);
    cudaGetSymbolAddress((void**)&prh,    g_pr_h);
    cudaGetSymbolAddress((void**)&prl,    g_pr_l);
    cudaGetSymbolAddress((void**)&ctxh,   g_ctx_h);
    cudaGetSymbolAddress((void**)&ctxl,   g_ctx_l);
    cudaGetSymbolAddress((void**)&mlphh,  g_mlph_h);
    cudaGetSymbolAddress((void**)&mlphl,  g_mlph_l);
    cudaGetSymbolAddress((void**)&wqkvTh, g_wqkvT_h);
    cudaGetSymbolAddress((void**)&wqkvTl, g_wqkvT_l);
    cudaGetSymbolAddress((void**)&woutTh, g_woutT_h);
    cudaGetSymbolAddress((void**)&woutTl, g_woutT_l);
    cudaGetSymbolAddress((void**)&wfiTh,  g_wfiT_h);
    cudaGetSymbolAddress((void**)&wfiTl,  g_wfiT_l);
    cudaGetSymbolAddress((void**)&wfoTh,  g_wfoT_h);
    cudaGetSymbolAddress((void**)&wfoTl,  g_wfoT_l);

    cudaFuncSetAttribute(gemm_mma, cudaFuncAttributeMaxDynamicSharedMemorySize, 2 * STAGE_B);
    const int GS = 2 * STAGE_B;
    dim3 tb(32, 8);

    // weight transpose + split
    wconv_kernel<<<dim3(3 * DM_ / 32, DM_ / 32),  tb>>>(w_qkv,    DM_,  3 * DM_, wqkvTh, wqkvTl);
    wconv_kernel<<<dim3(DM_ / 32,     DM_ / 32),  tb>>>(w_out,    DM_,  DM_,     woutTh, woutTl);
    wconv_kernel<<<dim3(DFF_ / 32,    DM_ / 32),  tb>>>(w_fc_in,  DM_,  DFF_,    wfiTh,  wfiTl);
    wconv_kernel<<<dim3(DM_ / 32,     DFF_ / 32), tb>>>(w_fc_out, DFF_, DM_,     wfoTh,  wfoTl);

    // 1. LayerNorm -> bf16 hi/lo
    ln_kernel<<<T_, 256>>>(hidden, ln_g, ln_b, lnh, lnl);

    // 2. QKV = ln @ w_qkv -> fp32
    gemm_mma<<<dim3(T_ / 128, 3 * DM_ / 128, 1), 256, GS>>>(
        lnh, lnl, DM_, 0, wqkvTh, wqkvTl, DM_, 0,
        qkv, 3 * DM_, 0, DM_, 0, 0.f, nullptr, nullptr, nullptr, nullptr, nullptr);

    // 3. RoPE + split q,k ; transpose + split v
    rope_split_kernel<<<T_, 256>>>(qkv, positions, qh, ql, kh, kl);
    vtrans_split_kernel<<<dim3(T_ / 32, HD_ / 32, H_), tb>>>(qkv, vTh, vTl);

    // 4. scores = scale * q @ k^T (tensor, causal tiles skipped)
    gemm_mma<<<dim3(T_ / 128, T_ / 128, H_), 256, GS>>>(
        qh, ql, DM_, HD_, kh, kl, DM_, HD_,
        scores, T_, (long)T_ * T_, HD_, 1, 0.0625f, nullptr, nullptr, nullptr, nullptr, nullptr);

    // 5. causal softmax -> probs bf16 hi/lo
    softmax_kernel<<<H_ * T_, 256>>>(scores, prh, prl);

    // 6. ctx = probs @ vT^T (tensor) -> bf16 hi/lo
    gemm_mma<<<dim3(T_ / 128, HD_ / 128, H_), 256, GS>>>(
        prh, prl, T_, (long)T_ * T_, vTh, vTl, T_, (long)HD_ * T_,
        nullptr, DM_, HD_, T_, 4, 0.f, nullptr, nullptr, nullptr, ctxh, ctxl);

    // 7. attn = ctx @ w_out -> fp32
    gemm_mma<<<dim3(T_ / 128, DM_ / 128, 1), 256, GS>>>(
        ctxh, ctxl, DM_, 0, woutTh, woutTl, DM_, 0,
        attn, DM_, 0, DM_, 0, 0.f, nullptr, nullptr, nullptr, nullptr, nullptr);

    // 8. mlph = gelu(ln @ w_fc_in + b) -> bf16 hi/lo
    gemm_mma<<<dim3(T_ / 128, DFF_ / 128, 1), 256, GS>>>(
        lnh, lnl, DM_, 0, wfiTh, wfiTl, DM_, 0,
        nullptr, DFF_, 0, DM_, 2, 0.f, b_fc_in, nullptr, nullptr, mlphh, mlphl);

    // 9. out = mlph @ w_fc_out + b + attn + residual
    gemm_mma<<<dim3(T_ / 128, DM_ / 128, 1), 256, GS>>>(
        mlphh, mlphl, DFF_, 0, wfoTh, wfoTl, DFF_, 0,
        out, DM_, 0, DFF_, 3, 0.f, b_fc_out, attn, hidden, nullptr, nullptr);
}

// round 7
// speedup vs baseline: 6.1672x; 1.7621x over previous
#include <cuda_runtime.h>
#include <cuda_fp16.h>
#include <math.h>
#include <stdint.h>

#define T_   2048
#define DM_  4096
#define H_   16
#define HD_  256
#define RD_  64
#define DFF_ 16384
#define EPS_ 1e-5f

// ==================== scratch (__device__ globals, no allocs) ====================
__device__ float g_qkv   [(long)T_ * 3 * DM_];
__device__ float g_scores[(long)H_ * T_ * T_];
__device__ float g_attn  [(long)T_ * DM_];
// split activations (fp16 hi/lo)
__device__ __half g_ln_h  [(long)T_ * DM_];
__device__ __half g_ln_l  [(long)T_ * DM_];
__device__ __half g_q_h   [(long)T_ * DM_];
__device__ __half g_q_l   [(long)T_ * DM_];
__device__ __half g_k_h   [(long)T_ * DM_];
__device__ __half g_k_l   [(long)T_ * DM_];
__device__ __half g_vT_h  [(long)H_ * HD_ * T_];
__device__ __half g_vT_l  [(long)H_ * HD_ * T_];
__device__ __half g_pr_h  [(long)H_ * T_ * T_];
__device__ __half g_pr_l  [(long)H_ * T_ * T_];
__device__ __half g_ctx_h [(long)T_ * DM_];
__device__ __half g_mlph_h[(long)T_ * DFF_];
// transposed (+ split) weights: [N][K] fp16
__device__ __half g_wqkvT_h[(long)3 * DM_ * DM_];
__device__ __half g_wqkvT_l[(long)3 * DM_ * DM_];
__device__ __half g_woutT_h[(long)DM_ * DM_];
__device__ __half g_wfiT_h [(long)DFF_ * DM_];
__device__ __half g_wfoT_h [(long)DM_ * DFF_];

// ==================== helpers ====================
__device__ __forceinline__ uint32_t smem_u32(const void* p) {
    uint32_t a;
    asm("{ .reg .u64 t; cvta.to.shared.u64 t, %1; cvt.u32.u64 %0, t; }" : "=r"(a) : "l"(p));
    return a;
}
#define CP_ASYNC16(dst, src) \
    asm volatile("cp.async.cg.shared.global [%0], [%1], 16;" :: "r"(dst), "l"(src) : "memory")
#define CP_COMMIT() asm volatile("cp.async.commit_group;" ::: "memory")
#define CP_WAIT1()  asm volatile("cp.async.wait_group 1;" ::: "memory")
#define LDMX4(r0, r1, r2, r3, addr) \
    asm volatile("ldmatrix.sync.aligned.m8n8.x4.shared.b16 {%0,%1,%2,%3}, [%4];" \
        : "=r"(r0), "=r"(r1), "=r"(r2), "=r"(r3) : "r"(addr))
#define MMA_F16(c0, c1, c2, c3, a0, a1, a2, a3, b0, b1) \
    asm volatile("mma.sync.aligned.m16n8k16.row.col.f32.f16.f16.f32 " \
        "{%0,%1,%2,%3}, {%4,%5,%6,%7}, {%8,%9}, {%0,%1,%2,%3};" \
        : "+f"(c0), "+f"(c1), "+f"(c2), "+f"(c3) \
        : "r"(a0), "r"(a1), "r"(a2), "r"(a3), "r"(b0), "r"(b1))

__device__ __forceinline__ float gelu_f(float v) {
    return 0.5f * v * (1.0f + tanhf(0.7978845608028654f * (v + 0.044715f * v * v * v)));
}
__device__ __forceinline__ uint32_t pack2h(float a, float b) {
    __half2 h = __floats2half2_rn(a, b);
    return *(uint32_t*)&h;
}
__device__ __forceinline__ uint32_t pack_hl(float a, float b, uint32_t& lo) {
    __half h0 = __float2half(a), h1 = __float2half(b);
    __half l0 = __float2half(a - __half2float(h0));
    __half l1 = __float2half(b - __half2float(h1));
    lo = ((uint32_t)__half_as_ushort(l1) << 16) | __half_as_ushort(l0);
    return ((uint32_t)__half_as_ushort(h1) << 16) | __half_as_ushort(h0);
}

// ==================== LayerNorm -> fp16 hi/lo ====================
__global__ void ln_kernel(const float* __restrict__ x, const float* __restrict__ g,
                          const float* __restrict__ b,
                          __half* __restrict__ oh, __half* __restrict__ ol)
{
    int row = blockIdx.x;
    const float* xr = x + (long)row * DM_;
    int tid = threadIdx.x;
    float s = 0.f, s2 = 0.f;
    #pragma unroll 4
    for (int i = tid; i < DM_; i += 256) { float v = xr[i]; s += v; s2 += v * v; }
    for (int o = 16; o > 0; o >>= 1) {
        s  += __shfl_xor_sync(0xffffffff, s,  o);
        s2 += __shfl_xor_sync(0xffffffff, s2, o);
    }
    __shared__ float ws[8], ws2[8];
    int wid = tid >> 5, lid = tid & 31;
    if (lid == 0) { ws[wid] = s; ws2[wid] = s2; }
    __syncthreads();
    if (wid == 0) {
        s  = (lid < 8) ? ws[lid]  : 0.f;
        s2 = (lid < 8) ? ws2[lid] : 0.f;
        for (int o = 4; o > 0; o >>= 1) {
            s  += __shfl_xor_sync(0xffffffff, s,  o);
            s2 += __shfl_xor_sync(0xffffffff, s2, o);
        }
        if (lid == 0) { ws[0] = s; ws2[0] = s2; }
    }
    __syncthreads();
    float mu  = ws[0]  * (1.0f / DM_);
    float var = ws2[0] * (1.0f / DM_) - mu * mu;
    float rs  = rsqrtf(var + EPS_);
    #pragma unroll 4
    for (int i = tid; i < DM_; i += 256) {
        float y = (xr[i] - mu) * rs * g[i] + b[i];
        __half h = __float2half(y);
        oh[(long)row * DM_ + i] = h;
        ol[(long)row * DM_ + i] = __float2half(y - __half2float(h));
    }
}

// ==================== weight transpose + fp16 split:  W[K,N] -> Th (+Tl) [N][K] ====================
__global__ void wconv_kernel(const float* __restrict__ W, int K, int N,
                             __half* __restrict__ Th, __half* __restrict__ Tl)
{
    __shared__ float tile[32][33];
    int n0 = blockIdx.x * 32, k0 = blockIdx.y * 32;
    int tx = threadIdx.x, ty = threadIdx.y;       // 32 x 8
    #pragma unroll
    for (int i = 0; i < 4; i++)
        tile[ty + 8 * i][tx] = W[(long)(k0 + ty + 8 * i) * N + n0 + tx];
    __syncthreads();
    #pragma unroll
    for (int i = 0; i < 4; i++) {
        float v = tile[tx][ty + 8 * i];
        __half h = __float2half(v);
        long o = (long)(n0 + ty + 8 * i) * K + k0 + tx;
        Th[o] = h;
        if (Tl) Tl[o] = __float2half(v - __half2float(h));
    }
}

// ==================== RoPE + split q,k -> fp16 hi/lo [T][DM] ====================
__global__ void rope_split_kernel(const float* __restrict__ qkv, const int* __restrict__ pos,
                                  __half* __restrict__ qh, __half* __restrict__ ql,
                                  __half* __restrict__ kh, __half* __restrict__ kl)
{
    int t = blockIdx.x;
    int tid = threadIdx.x;                         // 256
    const float* qrow = qkv + (long)t * (3 * DM_);
    const float* krow = qrow + DM_;
    float p = (float)pos[t];
    #pragma unroll
    for (int it = 0; it < 8; it++) {
        int pr = it * 256 + tid;                   // pair index 0..2047
        int h  = pr >> 7;
        int d2 = pr & 127;
        int base = h * HD_ + 2 * d2;
        float q1 = qrow[base], q2 = qrow[base + 1];
        float k1 = krow[base], k2 = krow[base + 1];
        if (d2 < RD_ / 2) {
            float freq = powf(10000.0f, -(float)d2 / (RD_ / 2));
            float sn, cs; sincosf(p * freq, &sn, &cs);
            float a = q1 * cs - q2 * sn, bq = q2 * cs + q1 * sn; q1 = a; q2 = bq;
            a = k1 * cs - k2 * sn; float bk = k2 * cs + k1 * sn; k1 = a; k2 = bk;
        }
        long o = ((long)t * DM_ + base) >> 1;      // u32 index
        uint32_t lo;
        ((uint32_t*)qh)[o] = pack_hl(q1, q2, lo); ((uint32_t*)ql)[o] = lo;
        ((uint32_t*)kh)[o] = pack_hl(k1, k2, lo); ((uint32_t*)kl)[o] = lo;
    }
}

// ==================== v transpose + split: vT[h][d][t] fp16 hi/lo ====================
__global__ void vtrans_split_kernel(const float* __restrict__ qkv,
                                    __half* __restrict__ vTh, __half* __restrict__ vTl)
{
    __shared__ float tile[32][33];
    int h = blockIdx.z;
    int t0 = blockIdx.x * 32, d0 = blockIdx.y * 32;
    int tx = threadIdx.x, ty = threadIdx.y;
    #pragma unroll
    for (int i = 0; i < 4; i++)
        tile[ty + 8 * i][tx] = qkv[(long)(t0 + ty + 8 * i) * (3 * DM_) + 2 * DM_ + h * HD_ + d0 + tx];
    __syncthreads();
    #pragma unroll
    for (int i = 0; i < 4; i++) {
        float v = tile[tx][ty + 8 * i];
        __half hh = __float2half(v);
        long o = ((long)h * HD_ + d0 + ty + 8 * i) * T_ + t0 + tx;
        vTh[o] = hh;
        vTl[o] = __float2half(v - __half2float(hh));
    }
}

// ==================== causal softmax: fp32 scores -> fp16 hi/lo probs ====================
__global__ void softmax_kernel(const float* __restrict__ scores,
                               __half* __restrict__ ph, __half* __restrict__ pl)
{
    long row = blockIdx.x;                 // h*T + t
    int t = (int)(row & (T_ - 1));
    int len = t + 1;
    int wlen = (t | 127) + 1;              // write bound (ctx GEMM reads k < this)
    const float* p = scores + row * T_;
    int tid = threadIdx.x;
    float mx = -3.4e38f;
    for (int i = tid; i < len; i += 256) mx = fmaxf(mx, p[i]);
    for (int o = 16; o > 0; o >>= 1) mx = fmaxf(mx, __shfl_xor_sync(0xffffffff, mx, o));
    __shared__ float sm[8];
    int wid = tid >> 5, lid = tid & 31;
    if (lid == 0) sm[wid] = mx;
    __syncthreads();
    if (tid < 8) {
        mx = sm[tid];
        for (int o = 4; o > 0; o >>= 1) mx = fmaxf(mx, __shfl_xor_sync(0xff, mx, o));
        if (tid == 0) sm[0] = mx;
    }
    __syncthreads();
    mx = sm[0];
    float sum = 0.f;
    for (int i = tid; i < len; i += 256) sum += __expf(p[i] - mx);
    for (int o = 16; o > 0; o >>= 1) sum += __shfl_xor_sync(0xffffffff, sum, o);
    __shared__ float ss[8];
    if (lid == 0) ss[wid] = sum;
    __syncthreads();
    if (tid < 8) {
        sum = ss[tid];
        for (int o = 4; o > 0; o >>= 1) sum += __shfl_xor_sync(0xff, sum, o);
        if (tid == 0) ss[0] = sum;
    }
    __syncthreads();
    float inv = 1.0f / ss[0];
    for (int i = tid; i < wlen; i += 256) {
        float e = (i < len) ? __expf(p[i] - mx) * inv : 0.f;
        __half hh = __float2half(e);
        ph[row * T_ + i] = hh;
        pl[row * T_ + i] = __float2half(e - __half2float(hh));
    }
}

// ==================== fp16-split mma.sync GEMM (batched by blockIdx.z) ====================
// npass 1: Ah*Bh    npass 2: + Al*Bh    npass 3: + Ah*Bl
// kcap: limit K to m0+128 (causal A = probs)
// mode 0: fp32 C                       mode 1: v*scale -> fp32 C, skip tiles above diag
// mode 2: gelu(v + bias[n]) -> Ch      mode 3: v + bias[n] + add1 + add2 -> fp32 C
// mode 4: plain -> Ch
#define AST 40   // smem row stride in fp16 elems (80 bytes, conflict-free ldmatrix)
#define STAGE_B 40960
#define MAT_B   10240

__global__ __launch_bounds__(256, 2)
void gemm_mma(const __half* __restrict__ Ah, const __half* __restrict__ Al,
              long lda, long hsA,
              const __half* __restrict__ Bh, const __half* __restrict__ Bl,
              long ldb, long hsB,
              float* __restrict__ C, long ldc, long hsC, int K,
              int npass, int kcap, int mode, float scale,
              const float* __restrict__ bias,
              const float* __restrict__ add1, const float* __restrict__ add2,
              __half* __restrict__ Ch)
{
    if (mode == 1 && blockIdx.y > blockIdx.x) return;   // fully-masked causal tile

    extern __shared__ char smem[];
    const uint32_t sbase = smem_u32(smem);
    const int tid = threadIdx.x, lane = tid & 31, wid = tid >> 5;
    const int warpM = wid >> 1, warpN = wid & 1;        // 4 x 2 warps
    const long m0 = (long)blockIdx.x * 128;
    const long n0 = (long)blockIdx.y * 128;
    const long z  = blockIdx.z;

    float acc[2][8][4];
    #pragma unroll
    for (int i = 0; i < 2; i++)
        #pragma unroll
        for (int j = 0; j < 8; j++)
            #pragma unroll
            for (int q = 0; q < 4; q++) acc[i][j][q] = 0.f;

    const __half* gA_h = Ah + z * hsA + m0 * lda;
    const __half* gA_l = Al ? (Al + z * hsA + m0 * lda) : gA_h;
    const __half* gB_h = Bh + z * hsB + n0 * ldb;
    const __half* gB_l = Bl ? (Bl + z * hsB + n0 * ldb) : gB_h;

    int Keff = K;
    if (kcap) { int lim = (int)m0 + 128; if (lim < Keff) Keff = lim; }
    const int nch = Keff >> 5;

    #define LOAD_STAGE(CH, S) do {                                              \
        const long k0_ = (long)(CH) << 5;                                       \
        const uint32_t so_ = sbase + (S) * STAGE_B;                             \
        _Pragma("unroll")                                                       \
        for (int j_ = 0; j_ < 2; j_++) {                                        \
            int idx_ = (j_ << 8) + tid;                                         \
            int row_ = idx_ >> 2, c16_ = idx_ & 3;                              \
            uint32_t doff_ = row_ * (AST * 2) + c16_ * 16;                      \
            long ga_ = (long)row_ * lda + k0_ + c16_ * 8;                       \
            long gb_ = (long)row_ * ldb + k0_ + c16_ * 8;                       \
            CP_ASYNC16(so_ + doff_, gA_h + ga_);                                \
            if (npass >= 2) CP_ASYNC16(so_ + MAT_B + doff_, gA_l + ga_);        \
            CP_ASYNC16(so_ + 2 * MAT_B + doff_, gB_h + gb_);                    \
            if (npass >= 3) CP_ASYNC16(so_ + 3 * MAT_B + doff_, gB_l + gb_);    \
        }                                                                       \
    } while (0)

    LOAD_STAGE(0, 0);
    CP_COMMIT();

    const int subA  = ((lane >> 3) & 1) * 8;
    const int subAk = ((lane >> 4)) * 8;
    const int subBr = ((lane >> 4)) * 8;
    const int subBk = ((lane >> 3) & 1) * 8;
    const int li = lane & 7;

    for (int ch = 0; ch < nch; ch++) {
        if (ch + 1 < nch) LOAD_STAGE(ch + 1, (ch + 1) & 1);
        CP_COMMIT();
        CP_WAIT1();
        __syncthreads();

        const uint32_t so = sbase + (ch & 1) * STAGE_B;
        const uint32_t sA_h = so;
        const uint32_t sA_l = so + MAT_B;
        const uint32_t sB_h = so + 2 * MAT_B;
        const uint32_t sB_l = so + 3 * MAT_B;

        #pragma unroll
        for (int ks = 0; ks < 2; ks++) {
            const int kk = ks * 16;
            uint32_t ah[2][4], al[2][4], bb[4][4];

            #pragma unroll
            for (int p = 0; p < 4; p++) {
                int r = warpN * 64 + p * 16 + subBr + li;
                int c = kk + subBk;
                LDMX4(bb[p][0], bb[p][1], bb[p][2], bb[p][3],
                      sB_h + (uint32_t)(r * (AST * 2) + c * 2));
            }
            #pragma unroll
            for (int mt = 0; mt < 2; mt++) {
                int r = warpM * 32 + mt * 16 + subA + li;
                int c = kk + subAk;
                LDMX4(ah[mt][0], ah[mt][1], ah[mt][2], ah[mt][3],
                      sA_h + (uint32_t)(r * (AST * 2) + c * 2));
            }
            #pragma unroll
            for (int mt = 0; mt < 2; mt++)
                #pragma unroll
                for (int nt = 0; nt < 8; nt++)
                    MMA_F16(acc[mt][nt][0], acc[mt][nt][1], acc[mt][nt][2], acc[mt][nt][3],
                            ah[mt][0], ah[mt][1], ah[mt][2], ah[mt][3],
                            bb[nt >> 1][(nt & 1) * 2], bb[nt >> 1][(nt & 1) * 2 + 1]);
            if (npass >= 2) {
                #pragma unroll
                for (int mt = 0; mt < 2; mt++) {
                    int r = warpM * 32 + mt * 16 + subA + li;
                    int c = kk + subAk;
                    LDMX4(al[mt][0], al[mt][1], al[mt][2], al[mt][3],
                          sA_l + (uint32_t)(r * (AST * 2) + c * 2));
                }
                #pragma unroll
                for (int mt = 0; mt < 2; mt++)
                    #pragma unroll
                    for (int nt = 0; nt < 8; nt++)
                        MMA_F16(acc[mt][nt][0], acc[mt][nt][1], acc[mt][nt][2], acc[mt][nt][3],
                                al[mt][0], al[mt][1], al[mt][2], al[mt][3],
                                bb[nt >> 1][(nt & 1) * 2], bb[nt >> 1][(nt & 1) * 2 + 1]);
            }
            if (npass >= 3) {
                #pragma unroll
                for (int p = 0; p < 4; p++) {
                    int r = warpN * 64 + p * 16 + subBr + li;
                    int c = kk + subBk;
                    LDMX4(bb[p][0], bb[p][1], bb[p][2], bb[p][3],
                          sB_l + (uint32_t)(r * (AST * 2) + c * 2));
                }
                #pragma unroll
                for (int mt = 0; mt < 2; mt++)
                    #pragma unroll
                    for (int nt = 0; nt < 8; nt++)
                        MMA_F16(acc[mt][nt][0], acc[mt][nt][1], acc[mt][nt][2], acc[mt][nt][3],
                                ah[mt][0], ah[mt][1], ah[mt][2], ah[mt][3],
                                bb[nt >> 1][(nt & 1) * 2], bb[nt >> 1][(nt & 1) * 2 + 1]);
            }
        }
        __syncthreads();
    }

    // ---- epilogue ----
    float* Cz = C ? (C + z * hsC) : nullptr;
    __half* Chz = Ch ? (Ch + z * hsC) : nullptr;
    const int qrow = lane >> 2;
    const int qcol = (lane & 3) * 2;
    #pragma unroll
    for (int mt = 0; mt < 2; mt++) {
        #pragma unroll
        for (int half = 0; half < 2; half++) {
            long m = m0 + warpM * 32 + mt * 16 + qrow + half * 8;
            #pragma unroll
            for (int nt = 0; nt < 8; nt++) {
                long n = n0 + warpN * 64 + nt * 8 + qcol;
                float v0 = acc[mt][nt][half * 2];
                float v1 = acc[mt][nt][half * 2 + 1];
                if (mode == 0) {
                    float2 o = {v0, v1};
                    *(float2*)(Cz + m * ldc + n) = o;
                } else if (mode == 1) {
                    float2 o = {v0 * scale, v1 * scale};
                    *(float2*)(Cz + m * ldc + n) = o;
                } else if (mode == 2) {
                    v0 = gelu_f(v0 + bias[n]);
                    v1 = gelu_f(v1 + bias[n + 1]);
                    *(uint32_t*)(Chz + m * ldc + n) = pack2h(v0, v1);
                } else if (mode == 3) {
                    float2 bv = *(const float2*)(bias + n);
                    float2 a1 = *(const float2*)(add1 + m * ldc + n);
                    float2 a2 = *(const float2*)(add2 + m * ldc + n);
                    float2 o = {v0 + bv.x + a1.x + a2.x, v1 + bv.y + a1.y + a2.y};
                    *(float2*)(Cz + m * ldc + n) = o;
                } else {
                    *(uint32_t*)(Chz + m * ldc + n) = pack2h(v0, v1);
                }
            }
        }
    }
}

// ==================== launch ====================
extern "C" void kernel_launch(void* const* d_in, const int* in_sizes, int n_in,
                              void* d_out, int out_size)
{
    const int*   positions = (const int*)  d_in[0];
    const float* hidden    = (const float*)d_in[1];
    const float* ln_g      = (const float*)d_in[2];
    const float* ln_b      = (const float*)d_in[3];
    const float* w_qkv     = (const float*)d_in[4];
    const float* w_out     = (const float*)d_in[5];
    const float* w_fc_in   = (const float*)d_in[6];
    const float* b_fc_in   = (const float*)d_in[7];
    const float* w_fc_out  = (const float*)d_in[8];
    const float* b_fc_out  = (const float*)d_in[9];
    float* out = (float*)d_out;

    float *qkv, *scores, *attn;
    __half *lnh, *lnl, *qh, *ql, *kh, *kl, *vTh, *vTl, *prh, *prl, *ctxh, *mlphh;
    __half *wqkvTh, *wqkvTl, *woutTh, *wfiTh, *wfoTh;
    cudaGetSymbolAddress((void**)&qkv,    g_qkv);
    cudaGetSymbolAddress((void**)&scores, g_scores);
    cudaGetSymbolAddress((void**)&attn,   g_attn);
    cudaGetSymbolAddress((void**)&lnh,    g_ln_h);
    cudaGetSymbolAddress((void**)&lnl,    g_ln_l);
    cudaGetSymbolAddress((void**)&qh,     g_q_h);
    cudaGetSymbolAddress((void**)&ql,     g_q_l);
    cudaGetSymbolAddress((void**)&kh,     g_k_h);
    cudaGetSymbolAddress((void**)&kl,     g_k_l);
    cudaGetSymbolAddress((void**)&vTh,    g_vT_h);
    cudaGetSymbolAddress((void**)&vTl,    g_vT_l);
    cudaGetSymbolAddress((void**)&prh,    g_pr_h);
    cudaGetSymbolAddress((void**)&prl,    g_pr_l);
    cudaGetSymbolAddress((void**)&ctxh,   g_ctx_h);
    cudaGetSymbolAddress((void**)&mlphh,  g_mlph_h);
    cudaGetSymbolAddress((void**)&wqkvTh, g_wqkvT_h);
    cudaGetSymbolAddress((void**)&wqkvTl, g_wqkvT_l);
    cudaGetSymbolAddress((void**)&woutTh, g_woutT_h);
    cudaGetSymbolAddress((void**)&wfiTh,  g_wfiT_h);
    cudaGetSymbolAddress((void**)&wfoTh,  g_wfoT_h);

    cudaFuncSetAttribute(gemm_mma, cudaFuncAttributeMaxDynamicSharedMemorySize, 2 * STAGE_B);
    const int GS = 2 * STAGE_B;
    dim3 tb(32, 8);

    // weight transpose + fp16 split (lo only for w_qkv)
    wconv_kernel<<<dim3(3 * DM_ / 32, DM_ / 32),  tb>>>(w_qkv,    DM_,  3 * DM_, wqkvTh, wqkvTl);
    wconv_kernel<<<dim3(DM_ / 32,     DM_ / 32),  tb>>>(w_out,    DM_,  DM_,     woutTh, nullptr);
    wconv_kernel<<<dim3(DFF_ / 32,    DM_ / 32),  tb>>>(w_fc_in,  DM_,  DFF_,    wfiTh,  nullptr);
    wconv_kernel<<<dim3(DM_ / 32,     DFF_ / 32), tb>>>(w_fc_out, DFF_, DM_,     wfoTh,  nullptr);

    // 1. LayerNorm -> fp16 hi/lo
    ln_kernel<<<T_, 256>>>(hidden, ln_g, ln_b, lnh, lnl);

    // 2. QKV = ln @ w_qkv  (3-pass, fp32 out)
    gemm_mma<<<dim3(T_ / 128, 3 * DM_ / 128, 1), 256, GS>>>(
        lnh, lnl, DM_, 0, wqkvTh, wqkvTl, DM_, 0,
        qkv, 3 * DM_, 0, DM_, 3, 0, 0, 0.f, nullptr, nullptr, nullptr, nullptr);

    // 3. RoPE + split q,k ; transpose + split v
    rope_split_kernel<<<T_, 256>>>(qkv, positions, qh, ql, kh, kl);
    vtrans_split_kernel<<<dim3(T_ / 32, HD_ / 32, H_), tb>>>(qkv, vTh, vTl);

    // 4. scores = scale * q @ k^T  (3-pass, causal tiles skipped)
    gemm_mma<<<dim3(T_ / 128, T_ / 128, H_), 256, GS>>>(
        qh, ql, DM_, HD_, kh, kl, DM_, HD_,
        scores, T_, (long)T_ * T_, HD_, 3, 0, 1, 0.0625f, nullptr, nullptr, nullptr, nullptr);

    // 5. causal softmax -> probs fp16 hi/lo
    softmax_kernel<<<H_ * T_, 256>>>(scores, prh, prl);

    // 6. ctx = probs @ vT^T  (3-pass, K capped at diagonal) -> fp16
    gemm_mma<<<dim3(T_ / 128, HD_ / 128, H_), 256, GS>>>(
        prh, prl, T_, (long)T_ * T_, vTh, vTl, T_, (long)HD_ * T_,
        nullptr, DM_, HD_, T_, 3, 1, 4, 0.f, nullptr, nullptr, nullptr, ctxh);

    // 7. attn = ctx @ w_out  (1-pass, fp32 out)
    gemm_mma<<<dim3(T_ / 128, DM_ / 128, 1), 256, GS>>>(
        ctxh, nullptr, DM_, 0, woutTh, nullptr, DM_, 0,
        attn, DM_, 0, DM_, 1, 0, 0, 0.f, nullptr, nullptr, nullptr, nullptr);

    // 8. mlph = gelu(ln @ w_fc_in + b)  (1-pass) -> fp16
    gemm_mma<<<dim3(T_ / 128, DFF_ / 128, 1), 256, GS>>>(
        lnh, nullptr, DM_, 0, wfiTh, nullptr, DM_, 0,
        nullptr, DFF_, 0, DM_, 1, 0, 2, 0.f, b_fc_in, nullptr, nullptr, mlphh);

    // 9. out = mlph @ w_fc_out + b + attn + residual  (1-pass)
    gemm_mma<<<dim3(T_ / 128, DM_ / 128, 1), 256, GS>>>(
        mlphh, nullptr, DFF_, 0, wfoTh, nullptr, DFF_, 0,
        out, DM_, 0, DFF_, 1, 0, 3, 0.f, b_fc_out, attn, hidden, nullptr);
}